// round 5
// baseline (speedup 1.0000x reference)
#include <cuda_runtime.h>
#include <cstdint>
#include <cstddef>

// ============================================================================
// Problem constants
// ============================================================================
#define N_TOK 8192
#define IN_F  4096
#define OUT_F 4096

// GEMM tiling
constexpr int TM = 128;            // CTA M
constexpr int TN = 256;            // CTA N
constexpr int TK = 64;             // K bytes per stage (64 int8)
constexpr int STAGES = 6;          // ring slots (pipeline depth 4)
constexpr int KITERS = IN_F / TK;  // 64
constexpr int STAGE_A = TM * TK;                  // 8192
constexpr int STAGE_BYTES = (TM + TN) * TK;       // 24576
constexpr int SMEM_TOTAL = STAGES * STAGE_BYTES;  // 147456

// ============================================================================
// Scratch: sign tensors in int8 (device globals — allocation-guard-safe)
// ============================================================================
__device__ int8_t g_xb[(size_t)N_TOK * IN_F];   // 32 MB
__device__ int8_t g_wb[(size_t)OUT_F * IN_F];   // 16 MB

// ============================================================================
// Helpers
// ============================================================================
__device__ __forceinline__ uint32_t smem_u32(const void* p) {
    uint32_t a;
    asm("{ .reg .u64 t; cvta.to.shared.u64 t, %1; cvt.u32.u64 %0, t; }"
        : "=r"(a) : "l"(p));
    return a;
}

__device__ __forceinline__ void cp_async16(uint32_t dst, const void* src) {
    asm volatile("cp.async.cg.shared.global [%0], [%1], 16;" :: "r"(dst), "l"(src));
}

__device__ __forceinline__ void ldmatrix_x4(uint32_t* r, uint32_t addr) {
    asm volatile(
        "ldmatrix.sync.aligned.m8n8.x4.shared.b16 {%0,%1,%2,%3}, [%4];"
        : "=r"(r[0]), "=r"(r[1]), "=r"(r[2]), "=r"(r[3]) : "r"(addr));
}

__device__ __forceinline__ void mma_s8(int* d, const uint32_t* a,
                                       uint32_t b0, uint32_t b1) {
    asm volatile(
        "mma.sync.aligned.m16n8k32.row.col.s32.s8.s8.s32 "
        "{%0,%1,%2,%3}, {%4,%5,%6,%7}, {%8,%9}, {%0,%1,%2,%3};"
        : "+r"(d[0]), "+r"(d[1]), "+r"(d[2]), "+r"(d[3])
        : "r"(a[0]), "r"(a[1]), "r"(a[2]), "r"(a[3]), "r"(b0), "r"(b1));
}

// ============================================================================
// Kernel 1: fp32 -> int8 sign (+1 / -1 / 0), 4 floats per thread
// ============================================================================
constexpr int NX4 = N_TOK * IN_F / 4;   // 8388608
constexpr int NW4 = OUT_F * IN_F / 4;   // 4194304

__device__ __forceinline__ int8_t sg(float f) {
    return (int8_t)((f > 0.0f) - (f < 0.0f));
}

__global__ void sign_convert_kernel(const float4* __restrict__ x,
                                    const float4* __restrict__ w) {
    int i = blockIdx.x * blockDim.x + threadIdx.x;
    float4 v;
    char4* dst;
    if (i < NX4) {
        v = x[i];
        dst = reinterpret_cast<char4*>(g_xb) + i;
    } else {
        int j = i - NX4;
        v = w[j];
        dst = reinterpret_cast<char4*>(g_wb) + j;
    }
    *dst = make_char4(sg(v.x), sg(v.y), sg(v.z), sg(v.w));
}

// ============================================================================
// Kernel 2: int8 mma.sync GEMM.
// CTA 128x256, 256 threads = 8 warps (2 M x 4 N), warp tile 64x64.
// 6-slot stage ring at pipeline depth 4, register double-buffered fragments,
// ONE __syncthreads + wait_group per TWO k-iterations (all SMEM writes inside
// a super-iteration target stages last read before the previous barrier).
//
// SMEM tile rows of 64B (4 x 16B chunks), swizzle: chunk ^= (row>>1)&3.
// ============================================================================

struct Frags {
    uint32_t a[4][4];
    uint32_t b[4][4];
};

__device__ __forceinline__ void load_frags(Frags& f, uint32_t sA, uint32_t sB,
                                           int ra, int rb, uint32_t swa,
                                           uint32_t swb, uint32_t ch) {
#pragma unroll
    for (int mf = 0; mf < 4; mf++)
        ldmatrix_x4(f.a[mf], sA + (ra + mf * 16) * 64 + ((ch ^ swa) * 16));
#pragma unroll
    for (int g = 0; g < 4; g++)
        ldmatrix_x4(f.b[g], sB + (rb + g * 16) * 64 + ((ch ^ swb) * 16));
}

__device__ __forceinline__ void mma_block(int acc[4][8][4], const Frags& f) {
#pragma unroll
    for (int mf = 0; mf < 4; mf++)
#pragma unroll
        for (int nf = 0; nf < 8; nf++) {
            const int g = nf >> 1;
            const uint32_t b0 = (nf & 1) ? f.b[g][1] : f.b[g][0];
            const uint32_t b1 = (nf & 1) ? f.b[g][3] : f.b[g][2];
            mma_s8(acc[mf][nf], f.a[mf], b0, b1);
        }
}

__device__ __forceinline__ void load_stage(uint32_t sbase, int s, int kt,
                                           int m0, int n0, int tid) {
    const uint32_t st = sbase + s * STAGE_BYTES;
    const int k0 = kt * TK;
    // A: 512 chunks, B: 1024 chunks; 6 per thread at 256 threads.
#pragma unroll
    for (int i = 0; i < 2; i++) {
        int idx = i * 256 + tid;
        int row = idx >> 2, c = idx & 3;
        uint32_t sw = (uint32_t)(c ^ ((row >> 1) & 3));
        cp_async16(st + row * 64 + sw * 16,
                   g_xb + (size_t)(m0 + row) * IN_F + k0 + c * 16);
    }
#pragma unroll
    for (int i = 0; i < 4; i++) {
        int idx = i * 256 + tid;
        int row = idx >> 2, c = idx & 3;
        uint32_t sw = (uint32_t)(c ^ ((row >> 1) & 3));
        cp_async16(st + STAGE_A + row * 64 + sw * 16,
                   g_wb + (size_t)(n0 + row) * IN_F + k0 + c * 16);
    }
}

__global__ void __launch_bounds__(256, 1)
binlinear_gemm(const float* __restrict__ bias, float* __restrict__ out) {
    extern __shared__ char smem[];
    const uint32_t sb = smem_u32(smem);
    const int tid = threadIdx.x;
    const int lid = tid & 31;
    const int wid = tid >> 5;
    const int wm = wid & 1;       // warp M row (0..1), tile 64
    const int wn = wid >> 1;      // warp N col (0..3), tile 64
    const int m0 = blockIdx.x * TM;
    const int n0 = blockIdx.y * TN;

    int acc[4][8][4];             // 128 regs
#pragma unroll
    for (int i = 0; i < 4; i++)
#pragma unroll
        for (int j = 0; j < 8; j++)
#pragma unroll
            for (int k = 0; k < 4; k++) acc[i][j][k] = 0;

    const int ra = wm * 64 + ((lid >> 3) & 1) * 8 + (lid & 7);
    const int rb = wn * 64 + ((lid >> 3) & 1) * 8 + (lid & 7);
    const int hi = lid >> 4;
    const uint32_t swa = (uint32_t)((ra >> 1) & 3);
    const uint32_t swb = (uint32_t)((rb >> 1) & 3);
    const uint32_t ch0 = (uint32_t)hi;        // ks0 chunk
    const uint32_t ch1 = (uint32_t)(2 + hi);  // ks1 chunk

    // Prologue: fill stages 0..3 with kt 0..3
#pragma unroll
    for (int s = 0; s < 4; s++) {
        load_stage(sb, s, s, m0, n0, tid);
        asm volatile("cp.async.commit_group;" ::: "memory");
    }
    // pending <= 1  =>  kt 0..2 complete
    asm volatile("cp.async.wait_group 1;" ::: "memory");
    __syncthreads();

    Frags f0, f1;
    load_frags(f0, sb, sb + STAGE_A, ra, rb, swa, swb, ch0);   // stage 0, ks0

    for (int it2 = 0; it2 < KITERS; it2 += 2) {
        const uint32_t s0 = sb + (it2 % STAGES) * STAGE_BYTES;
        const uint32_t s1 = sb + ((it2 + 1) % STAGES) * STAGE_BYTES;
        const uint32_t s2 = sb + ((it2 + 2) % STAGES) * STAGE_BYTES;

        // ---- iter it2 ----
        load_frags(f1, s0, s0 + STAGE_A, ra, rb, swa, swb, ch1);
        mma_block(acc, f0);
        load_frags(f0, s1, s1 + STAGE_A, ra, rb, swa, swb, ch0);
        mma_block(acc, f1);
        if (it2 + 4 < KITERS)
            load_stage(sb, (it2 + 4) % STAGES, it2 + 4, m0, n0, tid);
        asm volatile("cp.async.commit_group;" ::: "memory");

        // ---- iter it2+1 ----
        load_frags(f1, s1, s1 + STAGE_A, ra, rb, swa, swb, ch1);
        mma_block(acc, f0);
        if (it2 + 2 < KITERS)
            load_frags(f0, s2, s2 + STAGE_A, ra, rb, swa, swb, ch0);
        mma_block(acc, f1);
        if (it2 + 5 < KITERS)
            load_stage(sb, (it2 + 5) % STAGES, it2 + 5, m0, n0, tid);
        asm volatile("cp.async.commit_group;" ::: "memory");

        // pending <= 1  =>  kt <= it2+4 complete (covers next super-iter)
        asm volatile("cp.async.wait_group 1;" ::: "memory");
        __syncthreads();
    }

    // Epilogue: float2 stores + bias.
    const int er = m0 + wm * 64 + (lid >> 2);
    const int ec = n0 + wn * 64 + 2 * (lid & 3);
#pragma unroll
    for (int mf = 0; mf < 4; mf++) {
#pragma unroll
        for (int nf = 0; nf < 8; nf++) {
            const int r0 = er + mf * 16;
            const int c  = ec + nf * 8;
            const float b0 = bias[c], b1 = bias[c + 1];
            float2 v0, v1;
            v0.x = (float)acc[mf][nf][0] + b0;
            v0.y = (float)acc[mf][nf][1] + b1;
            v1.x = (float)acc[mf][nf][2] + b0;
            v1.y = (float)acc[mf][nf][3] + b1;
            *reinterpret_cast<float2*>(out + (size_t)r0 * OUT_F + c) = v0;
            *reinterpret_cast<float2*>(out + (size_t)(r0 + 8) * OUT_F + c) = v1;
        }
    }
}

// ============================================================================
// Launch
// ============================================================================
extern "C" void kernel_launch(void* const* d_in, const int* in_sizes, int n_in,
                              void* d_out, int out_size) {
    const float* x    = (const float*)d_in[0];
    const float* w    = (const float*)d_in[1];
    const float* bias = (const float*)d_in[2];
    float* out        = (float*)d_out;

    static bool attr_set = false;
    if (!attr_set) {
        cudaFuncSetAttribute(binlinear_gemm,
                             cudaFuncAttributeMaxDynamicSharedMemorySize,
                             SMEM_TOTAL);
        attr_set = true;
    }

    sign_convert_kernel<<<(NX4 + NW4) / 256, 256>>>(
        (const float4*)x, (const float4*)w);

    binlinear_gemm<<<dim3(N_TOK / TM, OUT_F / TN), 256, SMEM_TOTAL>>>(bias, out);
}

// round 6
// speedup vs baseline: 1.1164x; 1.1164x over previous
#include <cuda_runtime.h>
#include <cstdint>
#include <cstddef>

// ============================================================================
// Problem constants
// ============================================================================
#define N_TOK 8192
#define IN_F  4096
#define OUT_F 4096

// GEMM tiling
constexpr int TM = 128;            // CTA M
constexpr int TN = 256;            // CTA N
constexpr int TK = 64;             // K bytes per stage (64 int8)
constexpr int STAGES = 8;          // ring slots (pipeline depth 6)
constexpr int KITERS = IN_F / TK;  // 64
constexpr int STAGE_A = TM * TK;                  // 8192
constexpr int STAGE_BYTES = (TM + TN) * TK;       // 24576
constexpr int SMEM_TOTAL = STAGES * STAGE_BYTES;  // 196608

// ============================================================================
// Scratch: sign tensors in int8 (device globals — allocation-guard-safe)
// ============================================================================
__device__ int8_t g_xb[(size_t)N_TOK * IN_F];   // 32 MB
__device__ int8_t g_wb[(size_t)OUT_F * IN_F];   // 16 MB

// ============================================================================
// Helpers
// ============================================================================
__device__ __forceinline__ uint32_t smem_u32(const void* p) {
    uint32_t a;
    asm("{ .reg .u64 t; cvta.to.shared.u64 t, %1; cvt.u32.u64 %0, t; }"
        : "=r"(a) : "l"(p));
    return a;
}

__device__ __forceinline__ void cp_async16(uint32_t dst, const void* src) {
    asm volatile("cp.async.cg.shared.global [%0], [%1], 16;" :: "r"(dst), "l"(src));
}

__device__ __forceinline__ void ldmatrix_x4(uint32_t* r, uint32_t addr) {
    asm volatile(
        "ldmatrix.sync.aligned.m8n8.x4.shared.b16 {%0,%1,%2,%3}, [%4];"
        : "=r"(r[0]), "=r"(r[1]), "=r"(r[2]), "=r"(r[3]) : "r"(addr));
}

__device__ __forceinline__ void mma_s8(int* d, const uint32_t* a,
                                       uint32_t b0, uint32_t b1) {
    asm volatile(
        "mma.sync.aligned.m16n8k32.row.col.s32.s8.s8.s32 "
        "{%0,%1,%2,%3}, {%4,%5,%6,%7}, {%8,%9}, {%0,%1,%2,%3};"
        : "+r"(d[0]), "+r"(d[1]), "+r"(d[2]), "+r"(d[3])
        : "r"(a[0]), "r"(a[1]), "r"(a[2]), "r"(a[3]), "r"(b0), "r"(b1));
}

// ============================================================================
// Kernel 1: fp32 -> int8 sign (+1 / -1 / 0), 4 floats per thread
// ============================================================================
constexpr int NX4 = N_TOK * IN_F / 4;   // 8388608
constexpr int NW4 = OUT_F * IN_F / 4;   // 4194304

__device__ __forceinline__ int8_t sg(float f) {
    return (int8_t)((f > 0.0f) - (f < 0.0f));
}

__global__ void sign_convert_kernel(const float4* __restrict__ x,
                                    const float4* __restrict__ w) {
    int i = blockIdx.x * blockDim.x + threadIdx.x;
    float4 v;
    char4* dst;
    if (i < NX4) {
        v = x[i];
        dst = reinterpret_cast<char4*>(g_xb) + i;
    } else {
        int j = i - NX4;
        v = w[j];
        dst = reinterpret_cast<char4*>(g_wb) + j;
    }
    *dst = make_char4(sg(v.x), sg(v.y), sg(v.z), sg(v.w));
}

// ============================================================================
// Kernel 2: int8 mma.sync GEMM.
// CTA 128x256, 256 threads = 8 warps (2 M x 4 N), warp tile 64x64.
// 8-slot stage ring at pipeline depth 6, register double-buffered fragments,
// ONE __syncthreads + wait_group(2) per TWO k-iterations. The wait only ever
// targets groups committed a full super-iteration (~2800 cyc) earlier, so it
// never blocks on in-flight DRAM (the R5 mistake).
//
// SMEM tile rows of 64B (4 x 16B chunks), swizzle: chunk ^= (row>>1)&3.
// ============================================================================

struct Frags {
    uint32_t a[4][4];
    uint32_t b[4][4];
};

__device__ __forceinline__ void load_frags(Frags& f, uint32_t sA, uint32_t sB,
                                           int ra, int rb, uint32_t swa,
                                           uint32_t swb, uint32_t ch) {
#pragma unroll
    for (int mf = 0; mf < 4; mf++)
        ldmatrix_x4(f.a[mf], sA + (ra + mf * 16) * 64 + ((ch ^ swa) * 16));
#pragma unroll
    for (int g = 0; g < 4; g++)
        ldmatrix_x4(f.b[g], sB + (rb + g * 16) * 64 + ((ch ^ swb) * 16));
}

__device__ __forceinline__ void mma_block(int acc[4][8][4], const Frags& f) {
#pragma unroll
    for (int mf = 0; mf < 4; mf++)
#pragma unroll
        for (int nf = 0; nf < 8; nf++) {
            const int g = nf >> 1;
            const uint32_t b0 = (nf & 1) ? f.b[g][1] : f.b[g][0];
            const uint32_t b1 = (nf & 1) ? f.b[g][3] : f.b[g][2];
            mma_s8(acc[mf][nf], f.a[mf], b0, b1);
        }
}

__device__ __forceinline__ void load_stage(uint32_t sbase, int s, int kt,
                                           int m0, int n0, int tid) {
    const uint32_t st = sbase + s * STAGE_BYTES;
    const int k0 = kt * TK;
    // A: 512 chunks, B: 1024 chunks; 6 per thread at 256 threads.
#pragma unroll
    for (int i = 0; i < 2; i++) {
        int idx = i * 256 + tid;
        int row = idx >> 2, c = idx & 3;
        uint32_t sw = (uint32_t)(c ^ ((row >> 1) & 3));
        cp_async16(st + row * 64 + sw * 16,
                   g_xb + (size_t)(m0 + row) * IN_F + k0 + c * 16);
    }
#pragma unroll
    for (int i = 0; i < 4; i++) {
        int idx = i * 256 + tid;
        int row = idx >> 2, c = idx & 3;
        uint32_t sw = (uint32_t)(c ^ ((row >> 1) & 3));
        cp_async16(st + STAGE_A + row * 64 + sw * 16,
                   g_wb + (size_t)(n0 + row) * IN_F + k0 + c * 16);
    }
}

__global__ void __launch_bounds__(256, 1)
binlinear_gemm(const float* __restrict__ bias, float* __restrict__ out) {
    extern __shared__ char smem[];
    const uint32_t sb = smem_u32(smem);
    const int tid = threadIdx.x;
    const int lid = tid & 31;
    const int wid = tid >> 5;
    const int wm = wid & 1;       // warp M row (0..1), tile 64
    const int wn = wid >> 1;      // warp N col (0..3), tile 64
    const int m0 = blockIdx.x * TM;
    const int n0 = blockIdx.y * TN;

    int acc[4][8][4];             // 128 regs
#pragma unroll
    for (int i = 0; i < 4; i++)
#pragma unroll
        for (int j = 0; j < 8; j++)
#pragma unroll
            for (int k = 0; k < 4; k++) acc[i][j][k] = 0;

    const int ra = wm * 64 + ((lid >> 3) & 1) * 8 + (lid & 7);
    const int rb = wn * 64 + ((lid >> 3) & 1) * 8 + (lid & 7);
    const int hi = lid >> 4;
    const uint32_t swa = (uint32_t)((ra >> 1) & 3);
    const uint32_t swb = (uint32_t)((rb >> 1) & 3);
    const uint32_t ch0 = (uint32_t)hi;        // ks0 chunk
    const uint32_t ch1 = (uint32_t)(2 + hi);  // ks1 chunk

    // Prologue: fill stages 0..5 with kt 0..5
#pragma unroll
    for (int s = 0; s < 6; s++) {
        load_stage(sb, s, s, m0, n0, tid);
        asm volatile("cp.async.commit_group;" ::: "memory");
    }
    // pending <= 3  =>  kt 0..2 complete (covers super-iter 0 reads)
    asm volatile("cp.async.wait_group 3;" ::: "memory");
    __syncthreads();

    Frags f0, f1;
    load_frags(f0, sb, sb + STAGE_A, ra, rb, swa, swb, ch0);   // stage 0, ks0

    for (int it2 = 0; it2 < KITERS; it2 += 2) {
        const uint32_t s0 = sb + (it2 % STAGES) * STAGE_BYTES;
        const uint32_t s1 = sb + ((it2 + 1) % STAGES) * STAGE_BYTES;
        const uint32_t s2 = sb + ((it2 + 2) % STAGES) * STAGE_BYTES;

        // ---- iter it2 ----
        // Refill stage (it2+6)%8 = (it2-2)%8: last read in super-iter t-1,
        // i.e. before the barrier we just passed. Issue early for overlap.
        if (it2 + 6 < KITERS)
            load_stage(sb, (it2 + 6) % STAGES, it2 + 6, m0, n0, tid);
        asm volatile("cp.async.commit_group;" ::: "memory");

        load_frags(f1, s0, s0 + STAGE_A, ra, rb, swa, swb, ch1);
        mma_block(acc, f0);
        load_frags(f0, s1, s1 + STAGE_A, ra, rb, swa, swb, ch0);
        mma_block(acc, f1);

        // ---- iter it2+1 ----
        if (it2 + 7 < KITERS)
            load_stage(sb, (it2 + 7) % STAGES, it2 + 7, m0, n0, tid);
        asm volatile("cp.async.commit_group;" ::: "memory");

        load_frags(f1, s1, s1 + STAGE_A, ra, rb, swa, swb, ch1);
        mma_block(acc, f0);
        if (it2 + 2 < KITERS)
            load_frags(f0, s2, s2 + STAGE_A, ra, rb, swa, swb, ch0);
        mma_block(acc, f1);

        // pending <= 2  =>  kt <= it2+5 complete; next super-iter reads
        // kt <= it2+4. Newest waited group was committed last super-iter.
        asm volatile("cp.async.wait_group 2;" ::: "memory");
        __syncthreads();
    }

    // Epilogue: float2 stores + bias.
    const int er = m0 + wm * 64 + (lid >> 2);
    const int ec = n0 + wn * 64 + 2 * (lid & 3);
#pragma unroll
    for (int mf = 0; mf < 4; mf++) {
#pragma unroll
        for (int nf = 0; nf < 8; nf++) {
            const int r0 = er + mf * 16;
            const int c  = ec + nf * 8;
            const float b0 = bias[c], b1 = bias[c + 1];
            float2 v0, v1;
            v0.x = (float)acc[mf][nf][0] + b0;
            v0.y = (float)acc[mf][nf][1] + b1;
            v1.x = (float)acc[mf][nf][2] + b0;
            v1.y = (float)acc[mf][nf][3] + b1;
            *reinterpret_cast<float2*>(out + (size_t)r0 * OUT_F + c) = v0;
            *reinterpret_cast<float2*>(out + (size_t)(r0 + 8) * OUT_F + c) = v1;
        }
    }
}

// ============================================================================
// Launch
// ============================================================================
extern "C" void kernel_launch(void* const* d_in, const int* in_sizes, int n_in,
                              void* d_out, int out_size) {
    const float* x    = (const float*)d_in[0];
    const float* w    = (const float*)d_in[1];
    const float* bias = (const float*)d_in[2];
    float* out        = (float*)d_out;

    static bool attr_set = false;
    if (!attr_set) {
        cudaFuncSetAttribute(binlinear_gemm,
                             cudaFuncAttributeMaxDynamicSharedMemorySize,
                             SMEM_TOTAL);
        attr_set = true;
    }

    sign_convert_kernel<<<(NX4 + NW4) / 256, 256>>>(
        (const float4*)x, (const float4*)w);

    binlinear_gemm<<<dim3(N_TOK / TM, OUT_F / TN), 256, SMEM_TOTAL>>>(bias, out);
}